// round 4
// baseline (speedup 1.0000x reference)
#include <cuda_runtime.h>
#include <cuda_bf16.h>
#include <cstdint>

#define N_NODES  50000
#define N_EDGES  800000
#define N_GRAPHS 512
#define IN_C     128
#define HID      256
#define OUT_C    16

// ---------------- scratch (static device globals; no allocation) -------------
__device__ float g_agg [(size_t)N_NODES * HID];
__device__ float g_tmp [(size_t)N_NODES * HID];
__device__ float g_h   [(size_t)N_NODES * HID];
__device__ float g_pool[N_GRAPHS * HID];
__device__ int   g_deg   [N_NODES];
__device__ int   g_ex    [N_NODES];
__device__ int   g_bsums [128];
__device__ int   g_rowptr[N_NODES + 1];
__device__ int   g_cursor[N_NODES];
__device__ int   g_csr   [N_EDGES];
__device__ int   g_gstart[N_GRAPHS + 1];
__device__ int   g_is64;

// ---------------- int32/int64 index-width autodetect -------------------------
__global__ void detect_kernel(const unsigned int* __restrict__ w) {
    g_is64 = ((w[1] | w[3] | w[5] | w[7]) == 0u) ? 1 : 0;
}
__device__ __forceinline__ int idx_at(const void* p, long long i) {
    if (g_is64) return (int)((const long long*)p)[i];
    return ((const int*)p)[i];
}

// ---------------- CSR build ----------------------------------------------------
__global__ void zero_int(int* __restrict__ p, int n) {
    int i = blockIdx.x * blockDim.x + threadIdx.x;
    if (i < n) p[i] = 0;
}

__global__ void deg_hist(const void* __restrict__ ei, int* __restrict__ deg) {
    int e = blockIdx.x * blockDim.x + threadIdx.x;
    if (e >= N_EDGES) return;
    int d = idx_at(ei, (long long)N_EDGES + e);
    atomicAdd(&deg[d], 1);
}

#define SCAN_B 512
__global__ void scan1(const int* __restrict__ deg, int* __restrict__ ex,
                      int* __restrict__ sums) {
    __shared__ int s[SCAN_B];
    int b = blockIdx.x, t = threadIdx.x;
    int i = b * SCAN_B + t;
    int v = (i < N_NODES) ? deg[i] : 0;
    s[t] = v; __syncthreads();
    for (int off = 1; off < SCAN_B; off <<= 1) {
        int x = (t >= off) ? s[t - off] : 0;
        __syncthreads();
        s[t] += x;
        __syncthreads();
    }
    if (i < N_NODES) ex[i] = s[t] - v;
    if (t == SCAN_B - 1) sums[b] = s[t];
}

__global__ void scan2(int* __restrict__ sums, int nb) {
    __shared__ int s[128];
    int t = threadIdx.x;
    int v = (t < nb) ? sums[t] : 0;
    s[t] = v; __syncthreads();
    for (int off = 1; off < 128; off <<= 1) {
        int x = (t >= off) ? s[t - off] : 0;
        __syncthreads();
        s[t] += x;
        __syncthreads();
    }
    if (t < nb) sums[t] = s[t] - v;
}

__global__ void scan3(const int* __restrict__ ex, const int* __restrict__ sums,
                      int* __restrict__ rowptr, int* __restrict__ cursor) {
    int i = blockIdx.x * blockDim.x + threadIdx.x;
    if (i < N_NODES) {
        int v = ex[i] + sums[i >> 9];
        rowptr[i] = v;
        cursor[i] = v;
    }
    if (i == 0) rowptr[N_NODES] = N_EDGES;
}

__global__ void csr_fill(const void* __restrict__ ei, int* __restrict__ cursor,
                         int* __restrict__ csr) {
    int e = blockIdx.x * blockDim.x + threadIdx.x;
    if (e >= N_EDGES) return;
    int s = idx_at(ei, e);
    int d = idx_at(ei, (long long)N_EDGES + e);
    int p = atomicAdd(&cursor[d], 1);
    csr[p] = s;
}

// ---------------- aggregation: warp per node ----------------------------------
// NF4 float4 per lane (NF4=1 -> C=128, NF4=2 -> C=256). 8 nodes / 256-thr block.
template<int NF4>
__global__ void aggregate_w(const float4* __restrict__ h4,
                            const int* __restrict__ rowptr,
                            const int* __restrict__ csr,
                            float4* __restrict__ out)
{
    int node = blockIdx.x * 8 + (threadIdx.x >> 5);
    if (node >= N_NODES) return;
    int lane = threadIdx.x & 31;
    const int C4 = 32 * NF4;
    size_t nb = (size_t)node * C4;

    float4 acc[NF4];
    #pragma unroll
    for (int j = 0; j < NF4; j++) acc[j] = h4[nb + j * 32 + lane];

    int beg = rowptr[node], end = rowptr[node + 1];
    int e = beg;
    for (; e + 4 <= end; e += 4) {
        int s0 = csr[e], s1 = csr[e + 1], s2 = csr[e + 2], s3 = csr[e + 3];
        #pragma unroll
        for (int j = 0; j < NF4; j++) {
            float4 v0 = h4[(size_t)s0 * C4 + j * 32 + lane];
            float4 v1 = h4[(size_t)s1 * C4 + j * 32 + lane];
            float4 v2 = h4[(size_t)s2 * C4 + j * 32 + lane];
            float4 v3 = h4[(size_t)s3 * C4 + j * 32 + lane];
            acc[j].x += v0.x + v1.x + v2.x + v3.x;
            acc[j].y += v0.y + v1.y + v2.y + v3.y;
            acc[j].z += v0.z + v1.z + v2.z + v3.z;
            acc[j].w += v0.w + v1.w + v2.w + v3.w;
        }
    }
    for (; e < end; e++) {
        int s = csr[e];
        #pragma unroll
        for (int j = 0; j < NF4; j++) {
            float4 v = h4[(size_t)s * C4 + j * 32 + lane];
            acc[j].x += v.x; acc[j].y += v.y; acc[j].z += v.z; acc[j].w += v.w;
        }
    }
    #pragma unroll
    for (int j = 0; j < NF4; j++) out[nb + j * 32 + lane] = acc[j];
}

// ---------------- TF32 tensor GEMM, fragment-layout smem ----------------------
// 512 threads, 16 warps (4m x 4n), warp tile 32x32, BM=BN=128, BK=32.
// Smem holds tiles PRE-PERMUTED into m16n8k8 fragment order so every fragment
// load is one conflict-free LDS.128.
#define GBM 128
#define GBN 128
#define GBK 32
#define GNT 512
#define A_KS_STRIDE 1028   // 8*32*4 + 4 pad words (breaks STS bank collisions)
#define ASF_SIZE (4 * A_KS_STRIDE)
#define B_KS_STRIDE 1152   // 32 lanes * 36 words
#define BSF_SIZE (4 * B_KS_STRIDE)

__device__ __forceinline__ uint32_t f2tf32(float f) {
    uint32_t r;
    asm("cvt.rna.tf32.f32 %0, %1;" : "=r"(r) : "f"(f));
    return r;
}

__global__ __launch_bounds__(GNT, 1)
void gemm_tf32(const float* __restrict__ A,
               const float* __restrict__ W,      // K x N row-major
               const float* __restrict__ bias,   // N
               float* __restrict__ C,
               int M, int K, int N)
{
    __shared__ uint32_t Asf[ASF_SIZE];
    __shared__ uint32_t Bsf[BSF_SIZE];

    int bm = blockIdx.x * GBM;
    int bn = blockIdx.y * GBN;
    int tid  = threadIdx.x;
    int wid  = tid >> 5;
    int lane = tid & 31;
    int grp  = lane >> 2;
    int tig  = lane & 3;
    int wm = (wid & 3) * 32;    // warp row offset
    int wn = (wid >> 2) * 32;   // warp col offset

    float acc[2][4][4];
    #pragma unroll
    for (int i = 0; i < 2; i++)
        #pragma unroll
        for (int j = 0; j < 4; j++)
            #pragma unroll
            for (int r = 0; r < 4; r++) acc[i][j][r] = 0.f;

    float4 pa[2], pb[2];

    auto ld_tiles = [&](int k0) {
        #pragma unroll
        for (int i = 0; i < 2; i++) {
            int li = tid + i * GNT;          // 0..1023
            int r  = li >> 3;                // 0..127
            int cq = (li & 7) * 4;           // 0..28
            int row = bm + r;
            pa[i] = (row < M) ? *(const float4*)(A + (size_t)row * K + k0 + cq)
                              : make_float4(0.f, 0.f, 0.f, 0.f);
        }
        #pragma unroll
        for (int i = 0; i < 2; i++) {
            int li = tid + i * GNT;
            int kr = li >> 5;                // 0..31
            int nq = (li & 31) * 4;          // 0..124
            pb[i] = *(const float4*)(W + (size_t)(k0 + kr) * N + bn + nq);
        }
    };

    auto st_tiles = [&]() {
        // A: value (row r, k c) -> frag: ks=c>>3, mb=r>>4,
        // lane=(r&7)*4 + (c&3), reg=((r>>3)&1) + 2*((c&7)>>2)
        #pragma unroll
        for (int i = 0; i < 2; i++) {
            int li = tid + i * GNT;
            int r  = li >> 3;
            int cq = (li & 7) * 4;
            int ks = cq >> 3;
            int reg_hi = (cq & 7) >> 2;
            int mb = r >> 4, row16 = r & 15;
            uint32_t base = ks * A_KS_STRIDE + mb * 128
                          + (row16 & 7) * 4 * 4
                          + ((row16 >> 3) + 2 * reg_hi);
            float v[4] = {pa[i].x, pa[i].y, pa[i].z, pa[i].w};
            #pragma unroll
            for (int j = 0; j < 4; j++)
                Asf[base + j * 4] = f2tf32(v[j]);
        }
        // B: value (k kr, n) -> frag: ks=kr>>3, lane=(n&7)*4 + (kr&3),
        // nb=n>>3, reg=(kr&7)>>2; word = ks*BSTR + lane*36 + nb*2 + reg
        #pragma unroll
        for (int i = 0; i < 2; i++) {
            int li = tid + i * GNT;
            int kr = li >> 5;
            int nq = (li & 31) * 4;
            int ks = kr >> 3;
            int kc = kr & 7;
            int reg = kc >> 2;
            int tk  = kc & 3;
            int nb  = nq >> 3;
            int n8  = nq & 7;
            uint32_t base = ks * B_KS_STRIDE + nb * 2 + reg;
            float v[4] = {pb[i].x, pb[i].y, pb[i].z, pb[i].w};
            #pragma unroll
            for (int j = 0; j < 4; j++)
                Bsf[base + (uint32_t)((n8 + j) * 4 + tk) * 36] = f2tf32(v[j]);
        }
    };

    ld_tiles(0);

    for (int k0 = 0; k0 < K; k0 += GBK) {
        st_tiles();
        __syncthreads();
        if (k0 + GBK < K) ld_tiles(k0 + GBK);   // overlap next LDG with compute

        #pragma unroll
        for (int ks = 0; ks < 4; ks++) {
            uint32_t af[2][4];
            #pragma unroll
            for (int mt = 0; mt < 2; mt++) {
                int mb = (wm >> 4) + mt;
                *(uint4*)af[mt] =
                    *(const uint4*)&Asf[ks * A_KS_STRIDE + mb * 128 + lane * 4];
            }
            uint32_t bf[4][2];
            {
                uint32_t base = ks * B_KS_STRIDE + lane * 36 + (wn >> 3) * 2;
                uint4 t0 = *(const uint4*)&Bsf[base];
                uint4 t1 = *(const uint4*)&Bsf[base + 4];
                bf[0][0] = t0.x; bf[0][1] = t0.y;
                bf[1][0] = t0.z; bf[1][1] = t0.w;
                bf[2][0] = t1.x; bf[2][1] = t1.y;
                bf[3][0] = t1.z; bf[3][1] = t1.w;
            }
            #pragma unroll
            for (int mt = 0; mt < 2; mt++)
                #pragma unroll
                for (int nt = 0; nt < 4; nt++) {
                    asm volatile(
                        "mma.sync.aligned.m16n8k8.row.col.f32.tf32.tf32.f32 "
                        "{%0,%1,%2,%3}, {%4,%5,%6,%7}, {%8,%9}, {%0,%1,%2,%3};"
                        : "+f"(acc[mt][nt][0]), "+f"(acc[mt][nt][1]),
                          "+f"(acc[mt][nt][2]), "+f"(acc[mt][nt][3])
                        : "r"(af[mt][0]), "r"(af[mt][1]),
                          "r"(af[mt][2]), "r"(af[mt][3]),
                          "r"(bf[nt][0]), "r"(bf[nt][1]));
                }
        }
        __syncthreads();
    }

    // epilogue: bias + relu
    #pragma unroll
    for (int mt = 0; mt < 2; mt++) {
        #pragma unroll
        for (int nt = 0; nt < 4; nt++) {
            int col = bn + wn + nt * 8 + 2 * tig;
            float b0 = bias[col], b1 = bias[col + 1];
            int r0 = bm + wm + mt * 16 + grp;
            if (r0 < M) {
                float2 c;
                c.x = fmaxf(acc[mt][nt][0] + b0, 0.f);
                c.y = fmaxf(acc[mt][nt][1] + b1, 0.f);
                *(float2*)(C + (size_t)r0 * N + col) = c;
            }
            if (r0 + 8 < M) {
                float2 c;
                c.x = fmaxf(acc[mt][nt][2] + b0, 0.f);
                c.y = fmaxf(acc[mt][nt][3] + b1, 0.f);
                *(float2*)(C + (size_t)(r0 + 8) * N + col) = c;
            }
        }
    }
}

// ---------------- pooling over sorted batch -----------------------------------
__global__ void graph_bounds(const void* __restrict__ batch, int* __restrict__ gstart) {
    int g = blockIdx.x * blockDim.x + threadIdx.x;
    if (g > N_GRAPHS) return;
    int lo = 0, hi = N_NODES;
    while (lo < hi) {
        int mid = (lo + hi) >> 1;
        if (idx_at(batch, mid) < g) lo = mid + 1; else hi = mid;
    }
    gstart[g] = lo;
}

__global__ void pool_mean(const float* __restrict__ h,
                          const int* __restrict__ gstart,
                          float* __restrict__ pooled) {
    int g = blockIdx.x;
    int t = threadIdx.x;           // HID threads
    int beg = gstart[g], end = gstart[g + 1];
    float acc = 0.f;
    int n = beg;
    for (; n + 4 <= end; n += 4) {
        float a0 = h[(size_t)(n + 0) * HID + t];
        float a1 = h[(size_t)(n + 1) * HID + t];
        float a2 = h[(size_t)(n + 2) * HID + t];
        float a3 = h[(size_t)(n + 3) * HID + t];
        acc += a0 + a1 + a2 + a3;
    }
    for (; n < end; n++) acc += h[(size_t)n * HID + t];
    float c = fmaxf((float)(end - beg), 1.0f);
    pooled[(size_t)g * HID + t] = acc / c;
}

// ---------------- final MLP ---------------------------------------------------
__global__ void final_mlp(const float* __restrict__ pooled,
                          const float* __restrict__ w1, const float* __restrict__ b1,
                          const float* __restrict__ w2, const float* __restrict__ b2,
                          float* __restrict__ out) {
    __shared__ float p[HID];
    __shared__ float hh[HID];
    int g = blockIdx.x;
    int t = threadIdx.x;

    p[t] = pooled[(size_t)g * HID + t];
    __syncthreads();

    float acc = b1[t];
    #pragma unroll 8
    for (int k = 0; k < HID; k++)
        acc += p[k] * w1[(size_t)k * HID + t];
    hh[t] = fmaxf(acc, 0.f);
    __syncthreads();

    int o  = t >> 4;
    int kk = t & 15;
    float s = 0.f;
    for (int k = kk; k < HID; k += 16)
        s += hh[k] * w2[(size_t)k * OUT_C + o];
    #pragma unroll
    for (int off = 8; off; off >>= 1)
        s += __shfl_xor_sync(0xffffffffu, s, off);
    if (kk == 0) out[(size_t)g * OUT_C + o] = s + b2[o];
}

// ---------------- launcher ----------------------------------------------------
extern "C" void kernel_launch(void* const* d_in, const int* in_sizes, int n_in,
                              void* d_out, int out_size)
{
    const float* x     = (const float*)d_in[0];
    const void*  ei    = d_in[1];
    const void*  batch = d_in[2];
    const float* w[16];
    for (int i = 0; i < 16; i++) w[i] = (const float*)d_in[3 + i];
    float* out = (float*)d_out;

    float *agg, *tmp, *h, *pool;
    int *deg, *ex, *bsums, *rowptr, *cursor, *csr, *gstart;
    cudaGetSymbolAddress((void**)&agg,    g_agg);
    cudaGetSymbolAddress((void**)&tmp,    g_tmp);
    cudaGetSymbolAddress((void**)&h,      g_h);
    cudaGetSymbolAddress((void**)&pool,   g_pool);
    cudaGetSymbolAddress((void**)&deg,    g_deg);
    cudaGetSymbolAddress((void**)&ex,     g_ex);
    cudaGetSymbolAddress((void**)&bsums,  g_bsums);
    cudaGetSymbolAddress((void**)&rowptr, g_rowptr);
    cudaGetSymbolAddress((void**)&cursor, g_cursor);
    cudaGetSymbolAddress((void**)&csr,    g_csr);
    cudaGetSymbolAddress((void**)&gstart, g_gstart);

    detect_kernel<<<1, 1>>>((const unsigned int*)ei);

    // ---- CSR build (once, reused by all 3 layers) ----
    zero_int<<<(N_NODES + 255) / 256, 256>>>(deg, N_NODES);
    deg_hist<<<(N_EDGES + 255) / 256, 256>>>(ei, deg);
    int nb = (N_NODES + SCAN_B - 1) / SCAN_B;
    scan1<<<nb, SCAN_B>>>(deg, ex, bsums);
    scan2<<<1, 128>>>(bsums, nb);
    scan3<<<(N_NODES + 256) / 256, 256>>>(ex, bsums, rowptr, cursor);
    csr_fill<<<(N_EDGES + 255) / 256, 256>>>(ei, cursor, csr);

    // ---- 3 GIN layers ----
    for (int layer = 0; layer < 3; layer++) {
        const float* hin = (layer == 0) ? x : h;
        int K = (layer == 0) ? IN_C : HID;

        int nblocks = (N_NODES + 7) / 8;
        if (layer == 0)
            aggregate_w<1><<<nblocks, 256>>>((const float4*)hin, rowptr, csr,
                                             (float4*)agg);
        else
            aggregate_w<2><<<nblocks, 256>>>((const float4*)hin, rowptr, csr,
                                             (float4*)agg);

        dim3 grid((N_NODES + GBM - 1) / GBM, HID / GBN);
        gemm_tf32<<<grid, GNT>>>(agg, w[layer * 4 + 0], w[layer * 4 + 1],
                                 tmp, N_NODES, K, HID);
        gemm_tf32<<<grid, GNT>>>(tmp, w[layer * 4 + 2], w[layer * 4 + 3],
                                 h, N_NODES, HID, HID);
    }

    // ---- pooling (batch is sorted) ----
    graph_bounds<<<3, 256>>>(batch, gstart);
    pool_mean<<<N_GRAPHS, HID>>>(h, gstart, pool);

    final_mlp<<<N_GRAPHS, HID>>>(pool, w[12], w[13], w[14], w[15], out);
}

// round 5
// speedup vs baseline: 1.1178x; 1.1178x over previous
#include <cuda_runtime.h>
#include <cuda_bf16.h>
#include <cstdint>

#define N_NODES  50000
#define N_EDGES  800000
#define N_GRAPHS 512
#define IN_C     128
#define HID      256
#define OUT_C    16

// ---------------- scratch (static device globals; no allocation) -------------
__device__ float g_agg [(size_t)N_NODES * HID];
__device__ float g_tmp [(size_t)N_NODES * HID];
__device__ float g_h   [(size_t)N_NODES * HID];
__device__ float g_pool[N_GRAPHS * HID];
__device__ int   g_deg   [N_NODES];
__device__ int   g_ex    [N_NODES];
__device__ int   g_bsums [128];
__device__ int   g_rowptr[N_NODES + 1];
__device__ int   g_cursor[N_NODES];
__device__ int   g_csr   [N_EDGES];
__device__ int   g_gstart[N_GRAPHS + 1];
__device__ int   g_is64;

// ---------------- int32/int64 index-width autodetect -------------------------
__global__ void detect_kernel(const unsigned int* __restrict__ w) {
    g_is64 = ((w[1] | w[3] | w[5] | w[7]) == 0u) ? 1 : 0;
}
__device__ __forceinline__ int idx_at(const void* p, long long i) {
    if (g_is64) return (int)((const long long*)p)[i];
    return ((const int*)p)[i];
}

// ---------------- CSR build ----------------------------------------------------
__global__ void deg_hist(const void* __restrict__ ei, int* __restrict__ deg) {
    int e = blockIdx.x * blockDim.x + threadIdx.x;
    if (e >= N_EDGES) return;
    int d = idx_at(ei, (long long)N_EDGES + e);
    atomicAdd(&deg[d], 1);
}

#define SCAN_B 512
__global__ void scan1(const int* __restrict__ deg, int* __restrict__ ex,
                      int* __restrict__ sums) {
    __shared__ int s[SCAN_B];
    int b = blockIdx.x, t = threadIdx.x;
    int i = b * SCAN_B + t;
    int v = (i < N_NODES) ? deg[i] : 0;
    s[t] = v; __syncthreads();
    for (int off = 1; off < SCAN_B; off <<= 1) {
        int x = (t >= off) ? s[t - off] : 0;
        __syncthreads();
        s[t] += x;
        __syncthreads();
    }
    if (i < N_NODES) ex[i] = s[t] - v;
    if (t == SCAN_B - 1) sums[b] = s[t];
}

__global__ void scan2(int* __restrict__ sums, int nb) {   // single block, 128 thr
    __shared__ int s[128];
    int t = threadIdx.x;
    int v = (t < nb) ? sums[t] : 0;
    s[t] = v; __syncthreads();
    for (int off = 1; off < 128; off <<= 1) {
        int x = (t >= off) ? s[t - off] : 0;
        __syncthreads();
        s[t] += x;
        __syncthreads();
    }
    if (t < nb) sums[t] = s[t] - v;   // exclusive
}

__global__ void scan3(const int* __restrict__ ex, const int* __restrict__ sums,
                      int* __restrict__ rowptr, int* __restrict__ cursor) {
    int i = blockIdx.x * blockDim.x + threadIdx.x;
    if (i < N_NODES) {
        int v = ex[i] + sums[i >> 9];
        rowptr[i] = v;
        cursor[i] = v;
    }
    if (i == 0) rowptr[N_NODES] = N_EDGES;
}

__global__ void csr_fill(const void* __restrict__ ei, int* __restrict__ cursor,
                         int* __restrict__ csr) {
    int e = blockIdx.x * blockDim.x + threadIdx.x;
    if (e >= N_EDGES) return;
    int s = idx_at(ei, e);
    int d = idx_at(ei, (long long)N_EDGES + e);
    int p = atomicAdd(&cursor[d], 1);
    csr[p] = s;
}

// ---------------- aggregation: out[i] = h[i] + sum_{j in N(i)} h[j] ----------
// float4 lanes; C4 = C/4 threads per node, several nodes per 256-thread block.
__global__ void aggregate4(const float4* __restrict__ h4,
                           const int* __restrict__ rowptr,
                           const int* __restrict__ csr,
                           float4* __restrict__ out,
                           int c4shift)            // log2(C/4): 5 or 6
{
    int c4 = 1 << c4shift;
    int sub  = threadIdx.x >> c4shift;
    int t    = threadIdx.x & (c4 - 1);
    int npb  = 256 >> c4shift;
    int node = blockIdx.x * npb + sub;
    if (node >= N_NODES) return;

    int beg = rowptr[node], end = rowptr[node + 1];
    float4 acc = h4[((size_t)node << c4shift) + t];
    int e = beg;
    for (; e + 4 <= end; e += 4) {
        int s0 = csr[e], s1 = csr[e + 1], s2 = csr[e + 2], s3 = csr[e + 3];
        float4 v0 = h4[((size_t)s0 << c4shift) + t];
        float4 v1 = h4[((size_t)s1 << c4shift) + t];
        float4 v2 = h4[((size_t)s2 << c4shift) + t];
        float4 v3 = h4[((size_t)s3 << c4shift) + t];
        acc.x += v0.x + v1.x + v2.x + v3.x;
        acc.y += v0.y + v1.y + v2.y + v3.y;
        acc.z += v0.z + v1.z + v2.z + v3.z;
        acc.w += v0.w + v1.w + v2.w + v3.w;
    }
    for (; e < end; e++) {
        float4 v = h4[((size_t)csr[e] << c4shift) + t];
        acc.x += v.x; acc.y += v.y; acc.z += v.z; acc.w += v.w;
    }
    out[((size_t)node << c4shift) + t] = acc;
}

// ---------------- TF32 tensor-core GEMM: C = relu(A @ W + bias) ---------------
// R3 structure (measured best) + register prefetch of next k-slab.
#define GBM 128
#define GBN 128
#define GBK 32
#define ASTRIDE 36
#define BSTRIDE 136

__device__ __forceinline__ uint32_t f2tf32(float f) {
    uint32_t r;
    asm("cvt.rna.tf32.f32 %0, %1;" : "=r"(r) : "f"(f));
    return r;
}

__global__ __launch_bounds__(256, 2)
void gemm_tf32(const float* __restrict__ A,
               const float* __restrict__ W,      // K x N row-major
               const float* __restrict__ bias,   // N
               float* __restrict__ C,
               int M, int K, int N)
{
    __shared__ uint32_t As[GBM][ASTRIDE];
    __shared__ uint32_t Bs[GBK][BSTRIDE];

    int bm = blockIdx.x * GBM;
    int bn = blockIdx.y * GBN;
    int tid  = threadIdx.x;
    int wid  = tid >> 5;
    int lane = tid & 31;
    int grp  = lane >> 2;     // 0..7
    int tig  = lane & 3;      // 0..3
    int wm = (wid & 3) * 32;  // warp row offset in tile
    int wn = (wid >> 2) * 64; // warp col offset in tile

    float acc[2][8][4];
    #pragma unroll
    for (int i = 0; i < 2; i++)
        #pragma unroll
        for (int j = 0; j < 8; j++)
            #pragma unroll
            for (int r = 0; r < 4; r++) acc[i][j][r] = 0.f;

    float4 pa[4], pb[4];

    auto ld_tiles = [&](int k0) {
        #pragma unroll
        for (int i = 0; i < 4; i++) {
            int li = tid + i * 256;
            int r  = li >> 3;          // 0..127
            int cq = (li & 7) * 4;     // 0..28
            int row = bm + r;
            pa[i] = (row < M) ? *(const float4*)(A + (size_t)row * K + k0 + cq)
                              : make_float4(0.f, 0.f, 0.f, 0.f);
        }
        #pragma unroll
        for (int i = 0; i < 4; i++) {
            int li = tid + i * 256;
            int kr = li >> 5;          // 0..31
            int cq = (li & 31) * 4;    // 0..124
            pb[i] = *(const float4*)(W + (size_t)(k0 + kr) * N + bn + cq);
        }
    };

    auto st_tiles = [&]() {
        #pragma unroll
        for (int i = 0; i < 4; i++) {
            int li = tid + i * 256;
            int r  = li >> 3;
            int cq = (li & 7) * 4;
            As[r][cq + 0] = f2tf32(pa[i].x);
            As[r][cq + 1] = f2tf32(pa[i].y);
            As[r][cq + 2] = f2tf32(pa[i].z);
            As[r][cq + 3] = f2tf32(pa[i].w);
        }
        #pragma unroll
        for (int i = 0; i < 4; i++) {
            int li = tid + i * 256;
            int kr = li >> 5;
            int cq = (li & 31) * 4;
            Bs[kr][cq + 0] = f2tf32(pb[i].x);
            Bs[kr][cq + 1] = f2tf32(pb[i].y);
            Bs[kr][cq + 2] = f2tf32(pb[i].z);
            Bs[kr][cq + 3] = f2tf32(pb[i].w);
        }
    };

    ld_tiles(0);

    for (int k0 = 0; k0 < K; k0 += GBK) {
        st_tiles();
        __syncthreads();
        if (k0 + GBK < K) ld_tiles(k0 + GBK);   // hide LDG behind MMA phase

        #pragma unroll
        for (int ks = 0; ks < GBK; ks += 8) {
            uint32_t af[2][4];
            #pragma unroll
            for (int mt = 0; mt < 2; mt++) {
                int r0 = wm + mt * 16 + grp;
                af[mt][0] = As[r0][ks + tig];
                af[mt][1] = As[r0 + 8][ks + tig];
                af[mt][2] = As[r0][ks + tig + 4];
                af[mt][3] = As[r0 + 8][ks + tig + 4];
            }
            uint32_t bf[8][2];
            #pragma unroll
            for (int nt = 0; nt < 8; nt++) {
                int c0 = wn + nt * 8 + grp;
                bf[nt][0] = Bs[ks + tig][c0];
                bf[nt][1] = Bs[ks + tig + 4][c0];
            }
            #pragma unroll
            for (int mt = 0; mt < 2; mt++)
                #pragma unroll
                for (int nt = 0; nt < 8; nt++) {
                    asm volatile(
                        "mma.sync.aligned.m16n8k8.row.col.f32.tf32.tf32.f32 "
                        "{%0,%1,%2,%3}, {%4,%5,%6,%7}, {%8,%9}, {%0,%1,%2,%3};"
                        : "+f"(acc[mt][nt][0]), "+f"(acc[mt][nt][1]),
                          "+f"(acc[mt][nt][2]), "+f"(acc[mt][nt][3])
                        : "r"(af[mt][0]), "r"(af[mt][1]),
                          "r"(af[mt][2]), "r"(af[mt][3]),
                          "r"(bf[nt][0]), "r"(bf[nt][1]));
                }
        }
        __syncthreads();
    }

    // epilogue: bias + relu, float2 stores
    #pragma unroll
    for (int mt = 0; mt < 2; mt++) {
        #pragma unroll
        for (int nt = 0; nt < 8; nt++) {
            int col = bn + wn + nt * 8 + 2 * tig;
            float b0 = bias[col], b1 = bias[col + 1];
            int r0 = bm + wm + mt * 16 + grp;
            if (r0 < M) {
                float2 c;
                c.x = fmaxf(acc[mt][nt][0] + b0, 0.f);
                c.y = fmaxf(acc[mt][nt][1] + b1, 0.f);
                *(float2*)(C + (size_t)r0 * N + col) = c;
            }
            if (r0 + 8 < M) {
                float2 c;
                c.x = fmaxf(acc[mt][nt][2] + b0, 0.f);
                c.y = fmaxf(acc[mt][nt][3] + b1, 0.f);
                *(float2*)(C + (size_t)(r0 + 8) * N + col) = c;
            }
        }
    }
}

// ---------------- pooling over sorted batch -----------------------------------
__global__ void graph_bounds(const void* __restrict__ batch, int* __restrict__ gstart) {
    int g = blockIdx.x * blockDim.x + threadIdx.x;
    if (g > N_GRAPHS) return;
    int lo = 0, hi = N_NODES;
    while (lo < hi) {
        int mid = (lo + hi) >> 1;
        if (idx_at(batch, mid) < g) lo = mid + 1; else hi = mid;
    }
    gstart[g] = lo;
}

__global__ void pool_mean(const float* __restrict__ h,
                          const int* __restrict__ gstart,
                          float* __restrict__ pooled) {
    int g = blockIdx.x;
    int t = threadIdx.x;           // HID threads
    int beg = gstart[g], end = gstart[g + 1];
    float acc = 0.f;
    int n = beg;
    for (; n + 4 <= end; n += 4) {
        float a0 = h[(size_t)(n + 0) * HID + t];
        float a1 = h[(size_t)(n + 1) * HID + t];
        float a2 = h[(size_t)(n + 2) * HID + t];
        float a3 = h[(size_t)(n + 3) * HID + t];
        acc += a0 + a1 + a2 + a3;
    }
    for (; n < end; n++) acc += h[(size_t)n * HID + t];
    float c = fmaxf((float)(end - beg), 1.0f);
    pooled[(size_t)g * HID + t] = acc / c;
}

// ---------------- final MLP: out = relu(pooled@W1+b1)@W2+b2 ------------------
__global__ void final_mlp(const float* __restrict__ pooled,
                          const float* __restrict__ w1, const float* __restrict__ b1,
                          const float* __restrict__ w2, const float* __restrict__ b2,
                          float* __restrict__ out) {
    __shared__ float p[HID];
    __shared__ float hh[HID];
    int g = blockIdx.x;
    int t = threadIdx.x;

    p[t] = pooled[(size_t)g * HID + t];
    __syncthreads();

    float acc = b1[t];
    #pragma unroll 8
    for (int k = 0; k < HID; k++)
        acc += p[k] * w1[(size_t)k * HID + t];
    hh[t] = fmaxf(acc, 0.f);
    __syncthreads();

    int o  = t >> 4;
    int kk = t & 15;
    float s = 0.f;
    for (int k = kk; k < HID; k += 16)
        s += hh[k] * w2[(size_t)k * OUT_C + o];
    #pragma unroll
    for (int off = 8; off; off >>= 1)
        s += __shfl_xor_sync(0xffffffffu, s, off);
    if (kk == 0) out[(size_t)g * OUT_C + o] = s + b2[o];
}

// ---------------- launcher ----------------------------------------------------
extern "C" void kernel_launch(void* const* d_in, const int* in_sizes, int n_in,
                              void* d_out, int out_size)
{
    const float* x     = (const float*)d_in[0];
    const void*  ei    = d_in[1];
    const void*  batch = d_in[2];
    const float* w[16];
    for (int i = 0; i < 16; i++) w[i] = (const float*)d_in[3 + i];
    float* out = (float*)d_out;

    float *agg, *tmp, *h, *pool;
    int *deg, *ex, *bsums, *rowptr, *cursor, *csr, *gstart;
    cudaGetSymbolAddress((void**)&agg,    g_agg);
    cudaGetSymbolAddress((void**)&tmp,    g_tmp);
    cudaGetSymbolAddress((void**)&h,      g_h);
    cudaGetSymbolAddress((void**)&pool,   g_pool);
    cudaGetSymbolAddress((void**)&deg,    g_deg);
    cudaGetSymbolAddress((void**)&ex,     g_ex);
    cudaGetSymbolAddress((void**)&bsums,  g_bsums);
    cudaGetSymbolAddress((void**)&rowptr, g_rowptr);
    cudaGetSymbolAddress((void**)&cursor, g_cursor);
    cudaGetSymbolAddress((void**)&csr,    g_csr);
    cudaGetSymbolAddress((void**)&gstart, g_gstart);

    detect_kernel<<<1, 1>>>((const unsigned int*)ei);

    // ---- CSR build (once, reused by all 3 layers) ----
    cudaMemsetAsync(deg, 0, N_NODES * sizeof(int));
    deg_hist<<<(N_EDGES + 255) / 256, 256>>>(ei, deg);
    int nb = (N_NODES + SCAN_B - 1) / SCAN_B;   // 98
    scan1<<<nb, SCAN_B>>>(deg, ex, bsums);
    scan2<<<1, 128>>>(bsums, nb);
    scan3<<<(N_NODES + 256) / 256, 256>>>(ex, bsums, rowptr, cursor);
    csr_fill<<<(N_EDGES + 255) / 256, 256>>>(ei, cursor, csr);

    // ---- 3 GIN layers ----
    for (int layer = 0; layer < 3; layer++) {
        const float* hin = (layer == 0) ? x : h;
        int K = (layer == 0) ? IN_C : HID;
        int c4shift = (layer == 0) ? 5 : 6;
        int npb = 256 >> c4shift;

        aggregate4<<<(N_NODES + npb - 1) / npb, 256>>>(
            (const float4*)hin, rowptr, csr, (float4*)agg, c4shift);

        dim3 grid((N_NODES + GBM - 1) / GBM, HID / GBN);
        gemm_tf32<<<grid, 256>>>(agg, w[layer * 4 + 0], w[layer * 4 + 1],
                                 tmp, N_NODES, K, HID);
        gemm_tf32<<<grid, 256>>>(tmp, w[layer * 4 + 2], w[layer * 4 + 3],
                                 h, N_NODES, HID, HID);
    }

    // ---- pooling (batch is sorted) ----
    graph_bounds<<<3, 256>>>(batch, gstart);
    pool_mean<<<N_GRAPHS, HID>>>(h, gstart, pool);

    final_mlp<<<N_GRAPHS, HID>>>(pool, w[12], w[13], w[14], w[15], out);
}